// round 1
// baseline (speedup 1.0000x reference)
#include <cuda_runtime.h>

#define NN 100000
#define NE 3200000
#define NG 512
#define BN_EPS 1e-5f

// ---------------- scratch (static device allocations are the sanctioned path) ----
__device__ float g_agg1[NN * 4];
__device__ float g_A[NN * 64];     // lin1 output (reused by conv2)
__device__ float g_C[NN * 64];     // lin2 output (reused by conv2)
__device__ float g_h1[NN * 64];
__device__ float g_agg2[NN * 64];
__device__ float g_stats[512];     // 4 stages x (sum[64], sumsq[64])
__device__ float g_poolx[NG * 4];
__device__ float g_pool1[NG * 64];
__device__ float g_pool2[NG * 64];

__device__ __forceinline__ void red4(float* p, float4 v) {
    asm volatile("red.global.add.v4.f32 [%0], {%1,%2,%3,%4};"
                 :: "l"(p), "f"(v.x), "f"(v.y), "f"(v.z), "f"(v.w)
                 : "memory");
}

// ---------------- edge scatter, conv1 (4 floats / node) ------------------------
__global__ __launch_bounds__(256) void edge_scatter4(
    const int* __restrict__ src, const int* __restrict__ dst,
    const float4* __restrict__ x, float* __restrict__ agg)
{
    int e = blockIdx.x * blockDim.x + threadIdx.x;
    if (e >= NE) return;
    int s = src[e];
    int d = dst[e];
    float4 v = __ldg(&x[s]);
    red4(agg + (size_t)d * 4, v);
}

// ---------------- edge scatter, conv2 (64 floats / node), 4 threads per edge ---
__global__ __launch_bounds__(256) void edge_scatter64(
    const int* __restrict__ src, const int* __restrict__ dst,
    const float4* __restrict__ h, float* __restrict__ agg)
{
    int gid = blockIdx.x * blockDim.x + threadIdx.x;
    int e = gid >> 2;
    if (e >= NE) return;
    int c = gid & 3;
    int s = src[e];
    int d = dst[e];
    const float4* hp = h + (size_t)s * 16;
    float* ap = agg + (size_t)d * 64;
#pragma unroll
    for (int j = 0; j < 4; j++) {
        int idx = j * 4 + c;                 // lanes of an edge cover 64B contiguous
        float4 v = __ldg(&hp[idx]);
        red4(ap + idx * 4, v);
    }
}

// ---------------- conv1 lin1 (IN=4 -> 64) + stats -------------------------------
// block: 256 threads = 4 node-lanes x 64 feats; 16 node iterations per block
__global__ __launch_bounds__(256) void node_lin1(
    const float4* __restrict__ x, const float4* __restrict__ agg1,
    const float* __restrict__ w1, const float* __restrict__ b1,
    float* __restrict__ A, float* __restrict__ stats)
{
    int f = threadIdx.x & 63;
    int nl = threadIdx.x >> 6;
    float4 w = __ldg(&((const float4*)w1)[f]);
    float bias = __ldg(&b1[f]);
    float s = 0.f, q = 0.f;
    int base = blockIdx.x * 64;
#pragma unroll 4
    for (int it = 0; it < 16; it++) {
        int n = base + it * 4 + nl;
        if (n < NN) {
            float4 xv = x[n];
            float4 av = agg1[n];
            float hx = xv.x + av.x, hy = xv.y + av.y, hz = xv.z + av.z, hw = xv.w + av.w;
            float a = bias + hx * w.x + hy * w.y + hz * w.z + hw * w.w;
            A[(size_t)n * 64 + f] = a;
            s += a;
            q += a * a;
        }
    }
    __shared__ float ss[64], sq[64];
    if (threadIdx.x < 64) { ss[threadIdx.x] = 0.f; sq[threadIdx.x] = 0.f; }
    __syncthreads();
    atomicAdd(&ss[f], s);
    atomicAdd(&sq[f], q);
    __syncthreads();
    if (threadIdx.x < 64) {
        atomicAdd(&stats[threadIdx.x], ss[threadIdx.x]);
        atomicAdd(&stats[64 + threadIdx.x], sq[threadIdx.x]);
    }
}

// ---------------- 64x64 GEMM with fused prologue/epilogue ------------------------
// AMODE 0: A(n,k) = relu(bn(Araw[n,k]; stats_in, gamma, beta))
// AMODE 1: A(n,k) = Araw[n,k] + A2[n,k]
// C(n,f) = bias[f] + sum_k A(n,k) * W[f,k];  also accumulates stats of C.
// block: 128 threads, tile 64 nodes x 64 feats, thread tile 8 nodes x 4 feats.
template <int AMODE>
__global__ __launch_bounds__(128) void matmul64(
    const float* __restrict__ Araw, const float* __restrict__ A2,
    const float* __restrict__ stats_in,
    const float* __restrict__ gamma, const float* __restrict__ beta,
    const float* __restrict__ W, const float* __restrict__ bias,
    float* __restrict__ Cout, float* __restrict__ stats_out)
{
    __shared__ float sA[64 * 68];   // transposed: sA[k*68 + n]
    __shared__ float sW[64 * 68];   // transposed: sW[k*68 + f]
    __shared__ float sScale[64], sShift[64];
    __shared__ float s_rs[64], s_rq[64];

    int tid = threadIdx.x;
    int nbase = blockIdx.x * 64;

    if constexpr (AMODE == 0) {
        if (tid < 64) {
            float inv = 1.0f / NN;
            float m = stats_in[tid] * inv;
            float v = stats_in[64 + tid] * inv - m * m;
            float sc = gamma[tid] * rsqrtf(v + BN_EPS);
            sScale[tid] = sc;
            sShift[tid] = beta[tid] - m * sc;
        }
        __syncthreads();
    }

    for (int idx = tid; idx < 4096; idx += 128) {
        int n = idx >> 6, k = idx & 63;
        int gn = nbase + n;
        float a = 0.f;
        if (gn < NN) {
            if constexpr (AMODE == 0) {
                a = fmaxf(Araw[(size_t)gn * 64 + k] * sScale[k] + sShift[k], 0.f);
            } else {
                a = Araw[(size_t)gn * 64 + k] + A2[(size_t)gn * 64 + k];
            }
        }
        sA[k * 68 + n] = a;
        sW[k * 68 + n] = W[idx];   // idx = f*64 + k with f = idx>>6 == n here
    }
    __syncthreads();

    int ft = tid & 15;   // f0 = ft*4
    int nt = tid >> 4;   // n0 = nt*8
    float acc[8][4];
#pragma unroll
    for (int i = 0; i < 8; i++)
#pragma unroll
        for (int j = 0; j < 4; j++) acc[i][j] = 0.f;

#pragma unroll 4
    for (int k = 0; k < 64; k++) {
        float4 wv = *(const float4*)&sW[k * 68 + ft * 4];
        float4 a0 = *(const float4*)&sA[k * 68 + nt * 8];
        float4 a1 = *(const float4*)&sA[k * 68 + nt * 8 + 4];
        float av[8] = {a0.x, a0.y, a0.z, a0.w, a1.x, a1.y, a1.z, a1.w};
        float wl[4] = {wv.x, wv.y, wv.z, wv.w};
#pragma unroll
        for (int i = 0; i < 8; i++)
#pragma unroll
            for (int j = 0; j < 4; j++) acc[i][j] += av[i] * wl[j];
    }

    float bj[4];
#pragma unroll
    for (int j = 0; j < 4; j++) bj[j] = bias[ft * 4 + j];

    float ps[4] = {0.f, 0.f, 0.f, 0.f}, pq[4] = {0.f, 0.f, 0.f, 0.f};
#pragma unroll
    for (int i = 0; i < 8; i++) {
        int n = nbase + nt * 8 + i;
        if (n < NN) {
            float4 cv;
            cv.x = acc[i][0] + bj[0];
            cv.y = acc[i][1] + bj[1];
            cv.z = acc[i][2] + bj[2];
            cv.w = acc[i][3] + bj[3];
            *(float4*)&Cout[(size_t)n * 64 + ft * 4] = cv;
            ps[0] += cv.x; pq[0] += cv.x * cv.x;
            ps[1] += cv.y; pq[1] += cv.y * cv.y;
            ps[2] += cv.z; pq[2] += cv.z * cv.z;
            ps[3] += cv.w; pq[3] += cv.w * cv.w;
        }
    }

    if (tid < 64) { s_rs[tid] = 0.f; s_rq[tid] = 0.f; }
    __syncthreads();
#pragma unroll
    for (int j = 0; j < 4; j++) {
        atomicAdd(&s_rs[ft * 4 + j], ps[j]);
        atomicAdd(&s_rq[ft * 4 + j], pq[j]);
    }
    __syncthreads();
    if (tid < 64) {
        atomicAdd(&stats_out[tid], s_rs[tid]);
        atomicAdd(&stats_out[64 + tid], s_rq[tid]);
    }
}

// ---------------- BN + ReLU + pool (+ optional h store, + optional x pool) -------
__global__ __launch_bounds__(256) void bn_relu_pool(
    const float* __restrict__ Craw, const float* __restrict__ stats,
    const float* __restrict__ gamma, const float* __restrict__ betav,
    const int* __restrict__ batch,
    float* __restrict__ hout,        // nullable
    float* __restrict__ pool,
    const float4* __restrict__ xin,  // nullable
    float* __restrict__ poolx)       // nullable
{
    int gid = blockIdx.x * blockDim.x + threadIdx.x;
    if (gid >= NN * 16) return;
    int n = gid >> 4, c = gid & 15;
    int f0 = c * 4;
    float4 sum = *(const float4*)&stats[f0];
    float4 sq  = *(const float4*)&stats[64 + f0];
    float4 g4  = *(const float4*)&gamma[f0];
    float4 b4  = *(const float4*)&betav[f0];
    float inv = 1.0f / NN;

    float m, v, sc;
    float4 cv = *(const float4*)&Craw[(size_t)n * 64 + f0];
    float4 h;
    m = sum.x * inv; v = sq.x * inv - m * m; sc = g4.x * rsqrtf(v + BN_EPS);
    h.x = fmaxf(cv.x * sc + (b4.x - m * sc), 0.f);
    m = sum.y * inv; v = sq.y * inv - m * m; sc = g4.y * rsqrtf(v + BN_EPS);
    h.y = fmaxf(cv.y * sc + (b4.y - m * sc), 0.f);
    m = sum.z * inv; v = sq.z * inv - m * m; sc = g4.z * rsqrtf(v + BN_EPS);
    h.z = fmaxf(cv.z * sc + (b4.z - m * sc), 0.f);
    m = sum.w * inv; v = sq.w * inv - m * m; sc = g4.w * rsqrtf(v + BN_EPS);
    h.w = fmaxf(cv.w * sc + (b4.w - m * sc), 0.f);

    if (hout) *(float4*)&hout[(size_t)n * 64 + f0] = h;
    int b = batch[n];
    red4(&pool[(size_t)b * 64 + f0], h);
    if (xin && c == 0) red4(&poolx[(size_t)b * 4], __ldg(&xin[n]));
}

// ---------------- final: out = fc0(px)+fc1(p1)+fc2(p2); pi/vf heads --------------
__global__ __launch_bounds__(64) void final_heads(
    const float* __restrict__ poolx, const float* __restrict__ pool1, const float* __restrict__ pool2,
    const float* __restrict__ fc0_w, const float* __restrict__ fc0_b,
    const float* __restrict__ fc1_w, const float* __restrict__ fc1_b,
    const float* __restrict__ fc2_w, const float* __restrict__ fc2_b,
    const float* __restrict__ pi_w, const float* __restrict__ pi_b,
    const float* __restrict__ vf_w, const float* __restrict__ vf_b,
    float* __restrict__ out)
{
    int g = blockIdx.x;
    int f = threadIdx.x;
    __shared__ float s_out[64];

    float acc = fc0_b[f] + fc1_b[f] + fc2_b[f];
    float4 px = *(const float4*)&poolx[g * 4];
    float4 w0 = *(const float4*)&fc0_w[f * 4];
    acc += px.x * w0.x + px.y * w0.y + px.z * w0.z + px.w * w0.w;
#pragma unroll 8
    for (int k = 0; k < 64; k++) {
        acc += pool1[g * 64 + k] * fc1_w[f * 64 + k];
        acc += pool2[g * 64 + k] * fc2_w[f * 64 + k];
    }
    s_out[f] = acc;
    __syncthreads();

    float pi = pi_b[f], vf = vf_b[f];
#pragma unroll 8
    for (int k = 0; k < 64; k++) {
        float o = s_out[k];
        pi += o * pi_w[f * 64 + k];
        vf += o * vf_w[f * 64 + k];
    }
    out[g * 64 + f] = fmaxf(pi, 0.f);
    out[NG * 64 + g * 64 + f] = fmaxf(vf, 0.f);
}

// ---------------- launch ----------------------------------------------------------
extern "C" void kernel_launch(void* const* d_in, const int* in_sizes, int n_in,
                              void* d_out, int out_size)
{
    const float* x   = (const float*)d_in[0];
    const int* ei    = (const int*)d_in[1];
    const int* src   = ei;
    const int* dst   = ei + NE;
    const int* batch = (const int*)d_in[2];

    const float* c1_w1  = (const float*)d_in[3];
    const float* c1_b1  = (const float*)d_in[4];
    const float* c1_g1  = (const float*)d_in[5];
    const float* c1_be1 = (const float*)d_in[6];
    const float* c1_w2  = (const float*)d_in[7];
    const float* c1_b2  = (const float*)d_in[8];
    const float* bn1_g  = (const float*)d_in[9];
    const float* bn1_b  = (const float*)d_in[10];
    const float* c2_w1  = (const float*)d_in[11];
    const float* c2_b1  = (const float*)d_in[12];
    const float* c2_g1  = (const float*)d_in[13];
    const float* c2_be1 = (const float*)d_in[14];
    const float* c2_w2  = (const float*)d_in[15];
    const float* c2_b2  = (const float*)d_in[16];
    const float* bn2_g  = (const float*)d_in[17];
    const float* bn2_b  = (const float*)d_in[18];
    const float* fc0_w  = (const float*)d_in[19];
    const float* fc0_b  = (const float*)d_in[20];
    const float* fc1_w  = (const float*)d_in[21];
    const float* fc1_b  = (const float*)d_in[22];
    const float* fc2_w  = (const float*)d_in[23];
    const float* fc2_b  = (const float*)d_in[24];
    const float* pi_w   = (const float*)d_in[25];
    const float* pi_b   = (const float*)d_in[26];
    const float* vf_w   = (const float*)d_in[27];
    const float* vf_b   = (const float*)d_in[28];

    float *agg1, *agg2, *A, *C, *h1, *stats, *poolx, *pool1, *pool2;
    cudaGetSymbolAddress((void**)&agg1,  g_agg1);
    cudaGetSymbolAddress((void**)&agg2,  g_agg2);
    cudaGetSymbolAddress((void**)&A,     g_A);
    cudaGetSymbolAddress((void**)&C,     g_C);
    cudaGetSymbolAddress((void**)&h1,    g_h1);
    cudaGetSymbolAddress((void**)&stats, g_stats);
    cudaGetSymbolAddress((void**)&poolx, g_poolx);
    cudaGetSymbolAddress((void**)&pool1, g_pool1);
    cudaGetSymbolAddress((void**)&pool2, g_pool2);

    cudaMemsetAsync(agg1, 0, sizeof(float) * NN * 4);
    cudaMemsetAsync(agg2, 0, sizeof(float) * NN * 64);
    cudaMemsetAsync(stats, 0, sizeof(float) * 512);
    cudaMemsetAsync(poolx, 0, sizeof(float) * NG * 4);
    cudaMemsetAsync(pool1, 0, sizeof(float) * NG * 64);
    cudaMemsetAsync(pool2, 0, sizeof(float) * NG * 64);

    const int NB = (NN + 63) / 64;  // 1563

    // ---- conv1 ----
    edge_scatter4<<<(NE + 255) / 256, 256>>>(src, dst, (const float4*)x, agg1);
    node_lin1<<<NB, 256>>>((const float4*)x, (const float4*)agg1, c1_w1, c1_b1, A, stats + 0);
    matmul64<0><<<NB, 128>>>(A, nullptr, stats + 0, c1_g1, c1_be1, c1_w2, c1_b2, C, stats + 128);
    bn_relu_pool<<<(NN * 16 + 255) / 256, 256>>>(C, stats + 128, bn1_g, bn1_b, batch,
                                                 h1, pool1, (const float4*)x, poolx);

    // ---- conv2 ----
    edge_scatter64<<<(NE * 4 + 255) / 256, 256>>>(src, dst, (const float4*)h1, agg2);
    matmul64<1><<<NB, 128>>>(h1, agg2, nullptr, nullptr, nullptr, c2_w1, c2_b1, A, stats + 256);
    matmul64<0><<<NB, 128>>>(A, nullptr, stats + 256, c2_g1, c2_be1, c2_w2, c2_b2, C, stats + 384);
    bn_relu_pool<<<(NN * 16 + 255) / 256, 256>>>(C, stats + 384, bn2_g, bn2_b, batch,
                                                 nullptr, pool2, nullptr, nullptr);

    // ---- heads ----
    final_heads<<<NG, 64>>>(poolx, pool1, pool2,
                            fc0_w, fc0_b, fc1_w, fc1_b, fc2_w, fc2_b,
                            pi_w, pi_b, vf_w, vf_b, (float*)d_out);
}

// round 2
// speedup vs baseline: 1.1103x; 1.1103x over previous
#include <cuda_runtime.h>

#define NN 100000
#define NE 3200000
#define NG 512
#define BN_EPS 1e-5f
#define NBLK 391   // ceil(NN/256)

// ---------------- scratch -------------------------------------------------------
__device__ float g_agg1[NN * 4];
__device__ float g_A[NN * 64];
__device__ float g_C[NN * 64];
__device__ float g_h1[NN * 64];
__device__ float g_S[NN * 64];     // h1 + agg2 (gather64 output)
__device__ float g_stats[512];
__device__ float g_poolx[NG * 4];
__device__ float g_pool1[NG * 64];
__device__ float g_pool2[NG * 64];
__device__ int   g_deg[NN];
__device__ int   g_rowst[NN];
__device__ int   g_cursor[NN];
__device__ int   g_bsums[512];
__device__ int   g_csr[NE];

__device__ __forceinline__ void red4(float* p, float4 v) {
    asm volatile("red.global.add.v4.f32 [%0], {%1,%2,%3,%4};"
                 :: "l"(p), "f"(v.x), "f"(v.y), "f"(v.z), "f"(v.w)
                 : "memory");
}
__device__ __forceinline__ void red1(float* p, float v) {
    asm volatile("red.global.add.f32 [%0], %1;" :: "l"(p), "f"(v) : "memory");
}

// ---------------- CSR build -----------------------------------------------------
__global__ __launch_bounds__(256) void k_hist(const int* __restrict__ dst, int* __restrict__ deg) {
    int e = blockIdx.x * 256 + threadIdx.x;
    if (e < NE) atomicAdd(&deg[dst[e]], 1);
}

__global__ __launch_bounds__(256) void k_scan_block(const int* __restrict__ deg,
                                                    int* __restrict__ rowst, int* __restrict__ bsums) {
    int n = blockIdx.x * 256 + threadIdx.x;
    int v = (n < NN) ? deg[n] : 0;
    int lane = threadIdx.x & 31, wid = threadIdx.x >> 5;
    int x = v;
#pragma unroll
    for (int o = 1; o < 32; o <<= 1) { int y = __shfl_up_sync(~0u, x, o); if (lane >= o) x += y; }
    __shared__ int ws[8];
    if (lane == 31) ws[wid] = x;
    __syncthreads();
    if (threadIdx.x < 8) {
        int y = ws[threadIdx.x];
#pragma unroll
        for (int o = 1; o < 8; o <<= 1) { int z = __shfl_up_sync(0xff, y, o); if ((int)threadIdx.x >= o) y += z; }
        ws[threadIdx.x] = y;
    }
    __syncthreads();
    int base = wid ? ws[wid - 1] : 0;
    int incl = base + x;
    if (n < NN) rowst[n] = incl - v;
    if (threadIdx.x == 255) bsums[blockIdx.x] = incl;
}

__global__ __launch_bounds__(512) void k_scan_sums(int* __restrict__ bsums) {
    __shared__ int ws[16];
    int t = threadIdx.x;
    int v = (t < NBLK) ? bsums[t] : 0;
    int lane = t & 31, wid = t >> 5;
    int x = v;
#pragma unroll
    for (int o = 1; o < 32; o <<= 1) { int y = __shfl_up_sync(~0u, x, o); if (lane >= o) x += y; }
    if (lane == 31) ws[wid] = x;
    __syncthreads();
    if (t < 16) {
        int y = ws[t];
#pragma unroll
        for (int o = 1; o < 16; o <<= 1) { int z = __shfl_up_sync(0xffff, y, o); if (t >= o) y += z; }
        ws[t] = y;
    }
    __syncthreads();
    int base = wid ? ws[wid - 1] : 0;
    if (t < NBLK) bsums[t] = base + x - v;   // exclusive
}

__global__ __launch_bounds__(256) void k_scan_add(int* __restrict__ rowst, const int* __restrict__ bsums) {
    int n = blockIdx.x * 256 + threadIdx.x;
    if (n < NN) rowst[n] += bsums[blockIdx.x];
}

__global__ __launch_bounds__(256) void k_fill(const int* __restrict__ src, const int* __restrict__ dst,
                                              int* __restrict__ cursor, int* __restrict__ csr) {
    int e = blockIdx.x * 256 + threadIdx.x;
    if (e >= NE) return;
    int pos = atomicAdd(&cursor[dst[e]], 1);
    csr[pos] = src[e];
}

// ---------------- conv1 aggregate: thread per node (float4) ---------------------
__global__ __launch_bounds__(256) void gather4(
    const int* __restrict__ rowst, const int* __restrict__ deg, const int* __restrict__ csr,
    const float4* __restrict__ x, float4* __restrict__ agg)
{
    int n = blockIdx.x * 256 + threadIdx.x;
    if (n >= NN) return;
    int s = rowst[n], d = deg[n];
    float ax = 0.f, ay = 0.f, az = 0.f, aw = 0.f;
    int i = 0;
    for (; i + 4 <= d; i += 4) {
        int s0 = csr[s + i], s1 = csr[s + i + 1], s2 = csr[s + i + 2], s3 = csr[s + i + 3];
        float4 a = __ldg(&x[s0]), b = __ldg(&x[s1]), c = __ldg(&x[s2]), e = __ldg(&x[s3]);
        ax += (a.x + b.x) + (c.x + e.x);
        ay += (a.y + b.y) + (c.y + e.y);
        az += (a.z + b.z) + (c.z + e.z);
        aw += (a.w + b.w) + (c.w + e.w);
    }
    for (; i < d; i++) {
        float4 a = __ldg(&x[csr[s + i]]);
        ax += a.x; ay += a.y; az += a.z; aw += a.w;
    }
    agg[n] = make_float4(ax, ay, az, aw);
}

// ---------------- conv2 aggregate: warp per node, writes h1[n] + sum ------------
__global__ __launch_bounds__(256) void gather64(
    const int* __restrict__ rowst, const int* __restrict__ deg, const int* __restrict__ csr,
    const float2* __restrict__ h2, float2* __restrict__ out)
{
    int w = (blockIdx.x * 256 + threadIdx.x) >> 5;
    if (w >= NN) return;
    int lane = threadIdx.x & 31;
    int s = rowst[w], d = deg[w];
    float2 acc = h2[(size_t)w * 32 + lane];   // self term
    for (int base = 0; base < d; base += 32) {
        int cnt = min(32, d - base);
        int idx = (lane < cnt) ? csr[s + base + lane] : 0;
        int j = 0;
        for (; j + 4 <= cnt; j += 4) {
            int s0 = __shfl_sync(~0u, idx, j);
            int s1 = __shfl_sync(~0u, idx, j + 1);
            int s2 = __shfl_sync(~0u, idx, j + 2);
            int s3 = __shfl_sync(~0u, idx, j + 3);
            float2 v0 = __ldg(&h2[(size_t)s0 * 32 + lane]);
            float2 v1 = __ldg(&h2[(size_t)s1 * 32 + lane]);
            float2 v2 = __ldg(&h2[(size_t)s2 * 32 + lane]);
            float2 v3 = __ldg(&h2[(size_t)s3 * 32 + lane]);
            acc.x += (v0.x + v1.x) + (v2.x + v3.x);
            acc.y += (v0.y + v1.y) + (v2.y + v3.y);
        }
        for (; j < cnt; j++) {
            int s0 = __shfl_sync(~0u, idx, j);
            float2 v0 = __ldg(&h2[(size_t)s0 * 32 + lane]);
            acc.x += v0.x; acc.y += v0.y;
        }
    }
    out[(size_t)w * 32 + lane] = acc;
}

// ---------------- conv1 lin1 (IN=4 -> 64) + stats --------------------------------
__global__ __launch_bounds__(256) void node_lin1(
    const float4* __restrict__ x, const float4* __restrict__ agg1,
    const float* __restrict__ w1, const float* __restrict__ b1,
    float* __restrict__ A, float* __restrict__ stats)
{
    int f = threadIdx.x & 63;
    int nl = threadIdx.x >> 6;
    float4 w = __ldg(&((const float4*)w1)[f]);
    float bias = __ldg(&b1[f]);
    float s = 0.f, q = 0.f;
    int base = blockIdx.x * 64;
#pragma unroll 4
    for (int it = 0; it < 16; it++) {
        int n = base + it * 4 + nl;
        if (n < NN) {
            float4 xv = x[n];
            float4 av = agg1[n];
            float hx = xv.x + av.x, hy = xv.y + av.y, hz = xv.z + av.z, hw = xv.w + av.w;
            float a = bias + hx * w.x + hy * w.y + hz * w.z + hw * w.w;
            A[(size_t)n * 64 + f] = a;
            s += a; q += a * a;
        }
    }
    __shared__ float ss[64], sq[64];
    if (threadIdx.x < 64) { ss[threadIdx.x] = 0.f; sq[threadIdx.x] = 0.f; }
    __syncthreads();
    atomicAdd(&ss[f], s);
    atomicAdd(&sq[f], q);
    __syncthreads();
    if (threadIdx.x < 64) {
        red1(&stats[threadIdx.x], ss[threadIdx.x]);
        red1(&stats[64 + threadIdx.x], sq[threadIdx.x]);
    }
}

// ---------------- 64x64 GEMM with fused prologue/epilogue ------------------------
// AMODE 0: A = relu(bn(Araw)); AMODE 2: A = Araw
template <int AMODE>
__global__ __launch_bounds__(128) void matmul64(
    const float* __restrict__ Araw,
    const float* __restrict__ stats_in,
    const float* __restrict__ gamma, const float* __restrict__ beta,
    const float* __restrict__ W, const float* __restrict__ bias,
    float* __restrict__ Cout, float* __restrict__ stats_out)
{
    __shared__ float sA[64 * 68];
    __shared__ float sW[64 * 68];
    __shared__ float sScale[64], sShift[64];
    __shared__ float s_rs[64], s_rq[64];

    int tid = threadIdx.x;
    int nbase = blockIdx.x * 64;

    if constexpr (AMODE == 0) {
        if (tid < 64) {
            float inv = 1.0f / NN;
            float m = stats_in[tid] * inv;
            float v = stats_in[64 + tid] * inv - m * m;
            float sc = gamma[tid] * rsqrtf(v + BN_EPS);
            sScale[tid] = sc;
            sShift[tid] = beta[tid] - m * sc;
        }
        __syncthreads();
    }

    for (int idx = tid; idx < 4096; idx += 128) {
        int n = idx >> 6, k = idx & 63;
        int gn = nbase + n;
        float a = 0.f;
        if (gn < NN) {
            if constexpr (AMODE == 0)
                a = fmaxf(Araw[(size_t)gn * 64 + k] * sScale[k] + sShift[k], 0.f);
            else
                a = Araw[(size_t)gn * 64 + k];
        }
        sA[k * 68 + n] = a;
        sW[k * 68 + n] = W[idx];
    }
    __syncthreads();

    int ft = tid & 15;
    int nt = tid >> 4;
    float acc[8][4];
#pragma unroll
    for (int i = 0; i < 8; i++)
#pragma unroll
        for (int j = 0; j < 4; j++) acc[i][j] = 0.f;

#pragma unroll 4
    for (int k = 0; k < 64; k++) {
        float4 wv = *(const float4*)&sW[k * 68 + ft * 4];
        float4 a0 = *(const float4*)&sA[k * 68 + nt * 8];
        float4 a1 = *(const float4*)&sA[k * 68 + nt * 8 + 4];
        float av[8] = {a0.x, a0.y, a0.z, a0.w, a1.x, a1.y, a1.z, a1.w};
        float wl[4] = {wv.x, wv.y, wv.z, wv.w};
#pragma unroll
        for (int i = 0; i < 8; i++)
#pragma unroll
            for (int j = 0; j < 4; j++) acc[i][j] += av[i] * wl[j];
    }

    float bj[4];
#pragma unroll
    for (int j = 0; j < 4; j++) bj[j] = bias[ft * 4 + j];

    float ps[4] = {0.f, 0.f, 0.f, 0.f}, pq[4] = {0.f, 0.f, 0.f, 0.f};
#pragma unroll
    for (int i = 0; i < 8; i++) {
        int n = nbase + nt * 8 + i;
        if (n < NN) {
            float4 cv;
            cv.x = acc[i][0] + bj[0];
            cv.y = acc[i][1] + bj[1];
            cv.z = acc[i][2] + bj[2];
            cv.w = acc[i][3] + bj[3];
            *(float4*)&Cout[(size_t)n * 64 + ft * 4] = cv;
            ps[0] += cv.x; pq[0] += cv.x * cv.x;
            ps[1] += cv.y; pq[1] += cv.y * cv.y;
            ps[2] += cv.z; pq[2] += cv.z * cv.z;
            ps[3] += cv.w; pq[3] += cv.w * cv.w;
        }
    }

    if (tid < 64) { s_rs[tid] = 0.f; s_rq[tid] = 0.f; }
    __syncthreads();
#pragma unroll
    for (int j = 0; j < 4; j++) {
        atomicAdd(&s_rs[ft * 4 + j], ps[j]);
        atomicAdd(&s_rq[ft * 4 + j], pq[j]);
    }
    __syncthreads();
    if (tid < 64) {
        red1(&stats_out[tid], s_rs[tid]);
        red1(&stats_out[64 + tid], s_rq[tid]);
    }
}

// ---------------- BN + ReLU + pool (smem-staged, batch sorted) -------------------
__global__ __launch_bounds__(256) void bn_relu_pool(
    const float* __restrict__ Craw, const float* __restrict__ stats,
    const float* __restrict__ gamma, const float* __restrict__ betav,
    const int* __restrict__ batch,
    float* __restrict__ hout,        // nullable
    float* __restrict__ pool,
    const float4* __restrict__ xin,  // nullable
    float* __restrict__ poolx)       // nullable
{
    __shared__ float sc[64], sh[64];
    __shared__ float pacc[4 * 64];
    __shared__ float pxacc[4 * 4];
    int tid = threadIdx.x;
    int n0 = blockIdx.x * 64;

    if (tid < 64) {
        float inv = 1.0f / NN;
        float m = stats[tid] * inv;
        float v = stats[64 + tid] * inv - m * m;
        float s = gamma[tid] * rsqrtf(v + BN_EPS);
        sc[tid] = s;
        sh[tid] = betav[tid] - m * s;
    }
    pacc[tid] = 0.f;
    if (tid < 16) pxacc[tid] = 0.f;
    __syncthreads();

    int bmin = batch[n0 < NN ? n0 : NN - 1];
    int c = tid & 15, tg = tid >> 4;
    int f0 = c * 4;
    float4 s4 = *(const float4*)&sc[f0];
    float4 h4 = *(const float4*)&sh[f0];

    for (int it = 0; it < 4; it++) {
        int n = n0 + it * 16 + tg;
        if (n >= NN) break;
        float4 cv = *(const float4*)&Craw[(size_t)n * 64 + f0];
        float4 h;
        h.x = fmaxf(cv.x * s4.x + h4.x, 0.f);
        h.y = fmaxf(cv.y * s4.y + h4.y, 0.f);
        h.z = fmaxf(cv.z * s4.z + h4.z, 0.f);
        h.w = fmaxf(cv.w * s4.w + h4.w, 0.f);
        if (hout) *(float4*)&hout[(size_t)n * 64 + f0] = h;
        int b = batch[n];
        int off = b - bmin;
        if (off < 4) {
            float* p = &pacc[off * 64 + f0];
            atomicAdd(p, h.x); atomicAdd(p + 1, h.y);
            atomicAdd(p + 2, h.z); atomicAdd(p + 3, h.w);
            if (xin && c == 0) {
                float4 xv = __ldg(&xin[n]);
                float* q = &pxacc[off * 4];
                atomicAdd(q, xv.x); atomicAdd(q + 1, xv.y);
                atomicAdd(q + 2, xv.z); atomicAdd(q + 3, xv.w);
            }
        } else {
            red4(&pool[(size_t)b * 64 + f0], h);
            if (xin && c == 0) red4(&poolx[(size_t)b * 4], __ldg(&xin[n]));
        }
    }
    __syncthreads();
    {
        int slot = tid >> 6, f = tid & 63;
        int b = bmin + slot;
        float v = pacc[tid];
        if (b < NG && v != 0.f) red1(&pool[(size_t)b * 64 + f], v);
    }
    if (xin && tid < 16) {
        int slot = tid >> 2, f = tid & 3;
        int b = bmin + slot;
        float v = pxacc[tid];
        if (b < NG && v != 0.f) red1(&poolx[(size_t)b * 4 + f], v);
    }
}

// ---------------- final heads ----------------------------------------------------
__global__ __launch_bounds__(64) void final_heads(
    const float* __restrict__ poolx, const float* __restrict__ pool1, const float* __restrict__ pool2,
    const float* __restrict__ fc0_w, const float* __restrict__ fc0_b,
    const float* __restrict__ fc1_w, const float* __restrict__ fc1_b,
    const float* __restrict__ fc2_w, const float* __restrict__ fc2_b,
    const float* __restrict__ pi_w, const float* __restrict__ pi_b,
    const float* __restrict__ vf_w, const float* __restrict__ vf_b,
    float* __restrict__ out)
{
    int g = blockIdx.x;
    int f = threadIdx.x;
    __shared__ float s_out[64];

    float acc = fc0_b[f] + fc1_b[f] + fc2_b[f];
    float4 px = *(const float4*)&poolx[g * 4];
    float4 w0 = *(const float4*)&fc0_w[f * 4];
    acc += px.x * w0.x + px.y * w0.y + px.z * w0.z + px.w * w0.w;
#pragma unroll 8
    for (int k = 0; k < 64; k++) {
        acc += pool1[g * 64 + k] * fc1_w[f * 64 + k];
        acc += pool2[g * 64 + k] * fc2_w[f * 64 + k];
    }
    s_out[f] = acc;
    __syncthreads();

    float pi = pi_b[f], vf = vf_b[f];
#pragma unroll 8
    for (int k = 0; k < 64; k++) {
        float o = s_out[k];
        pi += o * pi_w[f * 64 + k];
        vf += o * vf_w[f * 64 + k];
    }
    out[g * 64 + f] = fmaxf(pi, 0.f);
    out[NG * 64 + g * 64 + f] = fmaxf(vf, 0.f);
}

// ---------------- launch ----------------------------------------------------------
extern "C" void kernel_launch(void* const* d_in, const int* in_sizes, int n_in,
                              void* d_out, int out_size)
{
    const float* x   = (const float*)d_in[0];
    const int* ei    = (const int*)d_in[1];
    const int* src   = ei;
    const int* dst   = ei + NE;
    const int* batch = (const int*)d_in[2];

    const float* c1_w1  = (const float*)d_in[3];
    const float* c1_b1  = (const float*)d_in[4];
    const float* c1_g1  = (const float*)d_in[5];
    const float* c1_be1 = (const float*)d_in[6];
    const float* c1_w2  = (const float*)d_in[7];
    const float* c1_b2  = (const float*)d_in[8];
    const float* bn1_g  = (const float*)d_in[9];
    const float* bn1_b  = (const float*)d_in[10];
    const float* c2_w1  = (const float*)d_in[11];
    const float* c2_b1  = (const float*)d_in[12];
    const float* c2_g1  = (const float*)d_in[13];
    const float* c2_be1 = (const float*)d_in[14];
    const float* c2_w2  = (const float*)d_in[15];
    const float* c2_b2  = (const float*)d_in[16];
    const float* bn2_g  = (const float*)d_in[17];
    const float* bn2_b  = (const float*)d_in[18];
    const float* fc0_w  = (const float*)d_in[19];
    const float* fc0_b  = (const float*)d_in[20];
    const float* fc1_w  = (const float*)d_in[21];
    const float* fc1_b  = (const float*)d_in[22];
    const float* fc2_w  = (const float*)d_in[23];
    const float* fc2_b  = (const float*)d_in[24];
    const float* pi_w   = (const float*)d_in[25];
    const float* pi_b   = (const float*)d_in[26];
    const float* vf_w   = (const float*)d_in[27];
    const float* vf_b   = (const float*)d_in[28];

    float *agg1, *A, *C, *h1, *S, *stats, *poolx, *pool1, *pool2;
    int *deg, *rowst, *cursor, *bsums, *csr;
    cudaGetSymbolAddress((void**)&agg1,  g_agg1);
    cudaGetSymbolAddress((void**)&A,     g_A);
    cudaGetSymbolAddress((void**)&C,     g_C);
    cudaGetSymbolAddress((void**)&h1,    g_h1);
    cudaGetSymbolAddress((void**)&S,     g_S);
    cudaGetSymbolAddress((void**)&stats, g_stats);
    cudaGetSymbolAddress((void**)&poolx, g_poolx);
    cudaGetSymbolAddress((void**)&pool1, g_pool1);
    cudaGetSymbolAddress((void**)&pool2, g_pool2);
    cudaGetSymbolAddress((void**)&deg,   g_deg);
    cudaGetSymbolAddress((void**)&rowst, g_rowst);
    cudaGetSymbolAddress((void**)&cursor,g_cursor);
    cudaGetSymbolAddress((void**)&bsums, g_bsums);
    cudaGetSymbolAddress((void**)&csr,   g_csr);

    cudaMemsetAsync(deg,   0, sizeof(int) * NN);
    cudaMemsetAsync(stats, 0, sizeof(float) * 512);
    cudaMemsetAsync(poolx, 0, sizeof(float) * NG * 4);
    cudaMemsetAsync(pool1, 0, sizeof(float) * NG * 64);
    cudaMemsetAsync(pool2, 0, sizeof(float) * NG * 64);

    const int NB = (NN + 63) / 64;          // 1563
    const int EB = (NE + 255) / 256;        // edge blocks

    // ---- CSR build (shared by both convs) ----
    k_hist<<<EB, 256>>>(dst, deg);
    k_scan_block<<<NBLK, 256>>>(deg, rowst, bsums);
    k_scan_sums<<<1, 512>>>(bsums);
    k_scan_add<<<NBLK, 256>>>(rowst, bsums);
    cudaMemcpyAsync(cursor, rowst, sizeof(int) * NN, cudaMemcpyDeviceToDevice);
    k_fill<<<EB, 256>>>(src, dst, cursor, csr);

    // ---- conv1 ----
    gather4<<<(NN + 255) / 256, 256>>>(rowst, deg, csr, (const float4*)x, (float4*)agg1);
    node_lin1<<<NB, 256>>>((const float4*)x, (const float4*)agg1, c1_w1, c1_b1, A, stats + 0);
    matmul64<0><<<NB, 128>>>(A, stats + 0, c1_g1, c1_be1, c1_w2, c1_b2, C, stats + 128);
    bn_relu_pool<<<NB, 256>>>(C, stats + 128, bn1_g, bn1_b, batch,
                              h1, pool1, (const float4*)x, poolx);

    // ---- conv2 ----
    gather64<<<(NN * 32 + 255) / 256, 256>>>(rowst, deg, csr, (const float2*)h1, (float2*)S);
    matmul64<2><<<NB, 128>>>(S, nullptr, nullptr, nullptr, c2_w1, c2_b1, A, stats + 256);
    matmul64<0><<<NB, 128>>>(A, stats + 256, c2_g1, c2_be1, c2_w2, c2_b2, C, stats + 384);
    bn_relu_pool<<<NB, 256>>>(C, stats + 384, bn2_g, bn2_b, batch,
                              nullptr, pool2, nullptr, nullptr);

    // ---- heads ----
    final_heads<<<NG, 64>>>(poolx, pool1, pool2,
                            fc0_w, fc0_b, fc1_w, fc1_b, fc2_w, fc2_b,
                            pi_w, pi_b, vf_w, vf_b, (float*)d_out);
}